// round 15
// baseline (speedup 1.0000x reference)
#include <cuda_runtime.h>
#include <cuda_fp16.h>
#include <math.h>
#include <stdint.h>

#define B_DIM   4096
#define ZDIM    128
#define IN_DIM  512
#define H_DIM   1024
#define SEQ_LEN 12
#define CAT     (IN_DIM + H_DIM)
#define LDO     (SEQ_LEN * IN_DIM)
#define N12     (2 * H_DIM)

typedef __half  f16;
typedef __half2 f162;

// ---------------- scratch (__device__ globals; no allocs allowed) -----------
__device__ float g_stf[B_DIM * H_DIM];
__device__ float g_spf[B_DIM * H_DIM];
__device__ float g_uf [B_DIM * H_DIM];

__device__ f16 g_tdh[B_DIM * LDO];
__device__ f16 g_zh [B_DIM * ZDIM];
__device__ f16 g_sph[B_DIM * H_DIM];
__device__ f16 g_sth[B_DIM * H_DIM];
__device__ f16 g_rsh[B_DIM * H_DIM];
__device__ f16 g_xh [B_DIM * IN_DIM];

// weights transposed to [N][K] fp16
__device__ f16 g_W12h[N12 * CAT];          // W1 rows then W2 rows
__device__ f16 g_W3h [H_DIM * CAT];
__device__ f16 g_Wbh [H_DIM * IN_DIM];
__device__ f16 g_Woh [IN_DIM * H_DIM];
__device__ f16 g_Wzh [IN_DIM * ZDIM];

enum { EPI_LIN = 0, EPI_BELTA = 1, EPI_SIGUR = 2, EPI_NEW = 3 };

// ---------------- prep kernels (3 launches) ---------------------------------
__global__ void zero_kernel(float* __restrict__ p, int n) {
    int i = blockIdx.x * blockDim.x + threadIdx.x;
    if (i < n) p[i] = 0.0f;
}

__global__ void ahalf2(const float* __restrict__ A, int n4a, f16* __restrict__ Ha,
                       const float* __restrict__ Bv, int n4b, f16* __restrict__ Hb) {
    int i = blockIdx.x * blockDim.x + threadIdx.x;
    if (i < n4a) {
        float4 v = ((const float4*)A)[i];
        ((f162*)Ha)[2 * i]     = __floats2half2_rn(v.x, v.y);
        ((f162*)Ha)[2 * i + 1] = __floats2half2_rn(v.z, v.w);
    } else if (i < n4a + n4b) {
        int j = i - n4a;
        float4 v = ((const float4*)Bv)[j];
        ((f162*)Hb)[2 * j]     = __floats2half2_rn(v.x, v.y);
        ((f162*)Hb)[2 * j + 1] = __floats2half2_rn(v.z, v.w);
    }
}

__global__ void wsplit_all(const float* __restrict__ W1, const float* __restrict__ W2,
                           const float* __restrict__ W3, const float* __restrict__ Wb,
                           const float* __restrict__ Wo, const float* __restrict__ Wz,
                           f16* __restrict__ T12, f16* __restrict__ T3,
                           f16* __restrict__ Tb, f16* __restrict__ To,
                           f16* __restrict__ Tz) {
    const float* W; f16* T; int K, N;
    switch (blockIdx.z) {
        case 0: W = W1; T = T12;                        K = CAT;    N = H_DIM;  break;
        case 1: W = W2; T = T12 + (size_t)H_DIM * CAT;  K = CAT;    N = H_DIM;  break;
        case 2: W = W3; T = T3;                         K = CAT;    N = H_DIM;  break;
        case 3: W = Wb; T = Tb;                         K = IN_DIM; N = H_DIM;  break;
        case 4: W = Wo; T = To;                         K = H_DIM;  N = IN_DIM; break;
        default: W = Wz; T = Tz;                        K = ZDIM;   N = IN_DIM; break;
    }
    const int n0 = blockIdx.x * 32, k0 = blockIdx.y * 32;
    if (n0 >= N || k0 >= K) return;
    __shared__ float t[32][33];
    const int tx = threadIdx.x, ty = threadIdx.y;   // (32, 8)
#pragma unroll
    for (int j = 0; j < 32; j += 8)
        t[ty + j][tx] = W[(size_t)(k0 + ty + j) * N + (n0 + tx)];
    __syncthreads();
#pragma unroll
    for (int j = 0; j < 32; j += 8)
        T[(size_t)(n0 + ty + j) * K + (k0 + tx)] = __float2half_rn(t[tx][ty + j]);
}

// ---------------- PTX primitives --------------------------------------------
__device__ __forceinline__ uint32_t smem_u32(const void* p) {
    uint32_t a;
    asm("{ .reg .u64 t; cvta.to.shared.u64 t, %1; cvt.u32.u64 %0, t; }" : "=r"(a) : "l"(p));
    return a;
}

#define CP16(dst, src) \
    asm volatile("cp.async.ca.shared.global [%0], [%1], 16;" :: "r"(dst), "l"(src) : "memory")
#define CPCOMMIT() asm volatile("cp.async.commit_group;" ::: "memory")
#define CPWAIT1()  asm volatile("cp.async.wait_group 1;"  ::: "memory")

#define LDSM4(r, a) \
    asm volatile("ldmatrix.sync.aligned.m8n8.x4.shared.b16 {%0,%1,%2,%3}, [%4];" \
        : "=r"((r)[0]), "=r"((r)[1]), "=r"((r)[2]), "=r"((r)[3]) : "r"(a))

#define MMA(c, a, b0, b1) \
    asm volatile("mma.sync.aligned.m16n8k16.row.col.f32.f16.f16.f32 " \
        "{%0,%1,%2,%3}, {%4,%5,%6,%7}, {%8,%9}, {%0,%1,%2,%3};" \
        : "+f"((c)[0]), "+f"((c)[1]), "+f"((c)[2]), "+f"((c)[3]) \
        : "r"((a)[0]), "r"((a)[1]), "r"((a)[2]), "r"((a)[3]), "r"(b0), "r"(b1))

// ---------------- 128x128 HMMA GEMM with fused epilogue (R13 core) ----------
#define KC      32
#define AROW80  80
#define TILE_B  (128 * AROW80)           // 10240 B
#define STAGE   (2 * TILE_B)             // A, B = 20480 B
#define NSTG    3
#define SMEM_T  (NSTG * STAGE)           // 61440 B

template <int EPI>
__global__ __launch_bounds__(256, 2)
void tgemm(const f16* __restrict__ Ah1, int lda1, int K1,
           const f16* __restrict__ Ah2, int lda2, int K2,
           const f16* __restrict__ Bh,
           const float* __restrict__ bias, const float* __restrict__ bias2,
           const float* __restrict__ ex1, const float* __restrict__ ex2,
           float* __restrict__ Cf, int ldcf,
           f16* __restrict__ Ch, int ldch)
{
    extern __shared__ __align__(128) char smem[];
    const uint32_t sb = smem_u32(smem);
    const int tid = threadIdx.x;
    const int bm = blockIdx.y * 128, bn = blockIdx.x * 128;
    const int Ktot = K1 + K2;
    const int KT = Ktot / KC;

    const int cr = tid >> 1;
    const int cs = (tid & 1) * 2;

    auto issue = [&](int c, int s) {
        const int ks = c * KC;
        const f16* ah = (ks < K1)
            ? Ah1 + (size_t)(bm + cr) * lda1 + ks
            : Ah2 + (size_t)(bm + cr) * lda2 + (ks - K1);
        const f16* bh = Bh + (size_t)(bn + cr) * Ktot + ks;
        const uint32_t base = sb + (uint32_t)s * STAGE + (uint32_t)cr * AROW80;
#pragma unroll
        for (int g = 0; g < 2; g++) {
            const int seg = cs + g;
            const uint32_t off = (uint32_t)seg * 16u;
            CP16(base + off,          ah + seg * 8);
            CP16(base + TILE_B + off, bh + seg * 8);
        }
    };

    const int warp = tid >> 5, lane = tid & 31;
    const int wm = (warp & 3) * 32;
    const int wn = (warp >> 2) * 64;
    const int lr = lane & 7;
    const uint32_t aBase = (uint32_t)(wm + lr + ((lane >> 3) & 1) * 8) * AROW80
                         + (uint32_t)(((lane >> 4) & 1) * 8) * 2;
    const uint32_t bBase = (uint32_t)(wn + lr + ((lane >> 4) & 1) * 8) * AROW80
                         + (uint32_t)(((lane >> 3) & 1) * 8) * 2;

    float acc[2][8][4];
#pragma unroll
    for (int mi = 0; mi < 2; mi++)
#pragma unroll
        for (int j = 0; j < 8; j++)
#pragma unroll
            for (int q = 0; q < 4; q++) acc[mi][j][q] = 0.0f;

    issue(0, 0); CPCOMMIT();
    issue(1, 1); CPCOMMIT();

    for (int c = 0; c < KT; c++) {
        CPWAIT1();
        __syncthreads();
        if (c + 2 < KT) issue(c + 2, (c + 2) % NSTG);
        CPCOMMIT();
        const uint32_t st = sb + (uint32_t)(c % NSTG) * STAGE;
#pragma unroll
        for (int k2 = 0; k2 < 2; k2++) {
            uint32_t ah[2][4];
#pragma unroll
            for (int mi = 0; mi < 2; mi++)
                LDSM4(ah[mi], st + aBase + (uint32_t)mi * (16 * AROW80)
                              + (uint32_t)k2 * 32);
#pragma unroll
            for (int jj = 0; jj < 4; jj++) {
                uint32_t b4[4];
                const uint32_t bo = st + TILE_B + bBase
                                  + (uint32_t)jj * (16 * AROW80) + (uint32_t)k2 * 32;
                LDSM4(b4, bo);
                MMA(acc[0][2 * jj],     ah[0], b4[0], b4[1]);
                MMA(acc[1][2 * jj],     ah[1], b4[0], b4[1]);
                MMA(acc[0][2 * jj + 1], ah[0], b4[2], b4[3]);
                MMA(acc[1][2 * jj + 1], ah[1], b4[2], b4[3]);
            }
        }
    }

    // --- epilogue ---
    const int r0 = bm + wm + (lane >> 2);
    const int c0 = bn + wn + 2 * (lane & 3);

    auto dopair = [&](int row, int col, float v0, float v1) {
        float2 bs = *(const float2*)(bias + col);
        v0 += bs.x; v1 += bs.y;
        if (EPI == EPI_BELTA) {
            float2 e = *(const float2*)(ex1 + (size_t)row * H_DIM + col);
            v0 = __expf(-fmaxf(v0, 0.0f)) * e.x;
            v1 = __expf(-fmaxf(v1, 0.0f)) * e.y;
        } else if (EPI == EPI_NEW) {
            float2 eu = *(const float2*)(ex1 + (size_t)row * H_DIM + col);
            float2 es = *(const float2*)(ex2 + (size_t)row * H_DIM + col);
            v0 = (1.0f - eu.x) * es.x + eu.x * tanhf(v0);
            v1 = (1.0f - eu.y) * es.y + eu.y * tanhf(v1);
        }
        if (Cf) *(float2*)(Cf + (size_t)row * ldcf + col) = make_float2(v0, v1);
        if (Ch) *(f162*)(Ch + (size_t)row * ldch + col) = __floats2half2_rn(v0, v1);
    };

#pragma unroll
    for (int mi = 0; mi < 2; mi++)
#pragma unroll
        for (int j = 0; j < 8; j++) {
            const int row = r0 + mi * 16;
            const int col = c0 + j * 8;
            dopair(row,     col, acc[mi][j][0], acc[mi][j][1]);
            dopair(row + 8, col, acc[mi][j][2], acc[mi][j][3]);
        }
}

// ---------------- 256x128 SIGUR GEMM: 512 threads, single-wave grid ---------
// 16 warps = 8(M) x 2(N), warp tile 32x64 (identical per-warp K-order -> bit-
// identical outputs). 2 CTAs/SM retained.
#define TA256   (256 * AROW80)           // 20480 B
#define STG256  (TA256 + TILE_B)         // 30720 B
#define SMEM256 (NSTG * STG256)          // 92160 B

__global__ __launch_bounds__(512, 2)
void tgemm512_sigur(const f16* __restrict__ Ah1, int lda1, int K1,
                    const f16* __restrict__ Ah2, int lda2, int K2,
                    const f16* __restrict__ Bh,
                    const float* __restrict__ bias, const float* __restrict__ bias2,
                    const float* __restrict__ ex1,
                    float* __restrict__ Cf, int ldcf,
                    f16* __restrict__ Ch, int ldch)
{
    extern __shared__ __align__(128) char smem[];
    const uint32_t sb = smem_u32(smem);
    const int tid = threadIdx.x;
    const int bm = blockIdx.y * 256, bn = blockIdx.x * 128;
    const int Ktot = K1 + K2;
    const int KT = Ktot / KC;

    // A: 256 rows, 2 threads/row, 2 segs each; B: 128 rows, 4 threads/row, 1 seg
    const int acr = tid >> 1, acs = (tid & 1) * 2;
    const int bcr = tid >> 2, bcs = tid & 3;

    auto issue = [&](int c, int s) {
        const int ks = c * KC;
        const f16* ah = (ks < K1)
            ? Ah1 + (size_t)(bm + acr) * lda1 + ks
            : Ah2 + (size_t)(bm + acr) * lda2 + (ks - K1);
        const uint32_t abase = sb + (uint32_t)s * STG256 + (uint32_t)acr * AROW80;
#pragma unroll
        for (int g = 0; g < 2; g++) {
            const int seg = acs + g;
            CP16(abase + (uint32_t)seg * 16u, ah + seg * 8);
        }
        const f16* bh = Bh + (size_t)(bn + bcr) * Ktot + ks;
        const uint32_t bbase = sb + (uint32_t)s * STG256 + TA256 + (uint32_t)bcr * AROW80;
        CP16(bbase + (uint32_t)bcs * 16u, bh + bcs * 8);
    };

    const int warp = tid >> 5, lane = tid & 31;
    const int wm = (warp & 7) * 32;            // 8 warps along M
    const int wn = (warp >> 3) * 64;           // 2 warps along N
    const int lr = lane & 7;
    const uint32_t aBase = (uint32_t)(wm + lr + ((lane >> 3) & 1) * 8) * AROW80
                         + (uint32_t)(((lane >> 4) & 1) * 8) * 2;
    const uint32_t bBase = (uint32_t)(wn + lr + ((lane >> 4) & 1) * 8) * AROW80
                         + (uint32_t)(((lane >> 3) & 1) * 8) * 2;

    float acc[2][8][4];
#pragma unroll
    for (int mi = 0; mi < 2; mi++)
#pragma unroll
        for (int j = 0; j < 8; j++)
#pragma unroll
            for (int q = 0; q < 4; q++) acc[mi][j][q] = 0.0f;

    issue(0, 0); CPCOMMIT();
    issue(1, 1); CPCOMMIT();

    for (int c = 0; c < KT; c++) {
        CPWAIT1();
        __syncthreads();
        if (c + 2 < KT) issue(c + 2, (c + 2) % NSTG);
        CPCOMMIT();
        const uint32_t st = sb + (uint32_t)(c % NSTG) * STG256;
#pragma unroll
        for (int k2 = 0; k2 < 2; k2++) {
            uint32_t ah[2][4];
#pragma unroll
            for (int mi = 0; mi < 2; mi++)
                LDSM4(ah[mi], st + aBase + (uint32_t)mi * (16 * AROW80)
                              + (uint32_t)k2 * 32);
#pragma unroll
            for (int jj = 0; jj < 4; jj++) {
                uint32_t b4[4];
                const uint32_t bo = st + TA256 + bBase
                                  + (uint32_t)jj * (16 * AROW80) + (uint32_t)k2 * 32;
                LDSM4(b4, bo);
                MMA(acc[0][2 * jj],     ah[0], b4[0], b4[1]);
                MMA(acc[1][2 * jj],     ah[1], b4[0], b4[1]);
                MMA(acc[0][2 * jj + 1], ah[0], b4[2], b4[3]);
                MMA(acc[1][2 * jj + 1], ah[1], b4[2], b4[3]);
            }
        }
    }

    // --- SIGUR epilogue ---
    const int r0 = bm + wm + (lane >> 2);
    const int c0 = bn + wn + 2 * (lane & 3);

    auto dopair = [&](int row, int col, float v0, float v1) {
        if (col < H_DIM) {
            float2 bs = *(const float2*)(bias + col);
            v0 = 1.0f / (1.0f + __expf(-(v0 + bs.x)));
            v1 = 1.0f / (1.0f + __expf(-(v1 + bs.y)));
            *(float2*)(Cf + (size_t)row * ldcf + col) = make_float2(v0, v1);
        } else {
            const int cc = col - H_DIM;
            float2 bs = *(const float2*)(bias2 + cc);
            float2 e  = *(const float2*)(ex1 + (size_t)row * H_DIM + cc);
            v0 = e.x / (1.0f + __expf(-(v0 + bs.x)));
            v1 = e.y / (1.0f + __expf(-(v1 + bs.y)));
            *(f162*)(Ch + (size_t)row * ldch + cc) = __floats2half2_rn(v0, v1);
        }
    };

#pragma unroll
    for (int mi = 0; mi < 2; mi++)
#pragma unroll
        for (int j = 0; j < 8; j++) {
            const int row = r0 + mi * 16;
            const int col = c0 + j * 8;
            dopair(row,     col, acc[mi][j][0], acc[mi][j][1]);
            dopair(row + 8, col, acc[mi][j][2], acc[mi][j][3]);
        }
}

// ---------------- 64x128 LIN GEMM (OUT / x0) --------------------------------
#define TA64    (64 * AROW80)            // 5120 B
#define STG64   (TA64 + TILE_B)          // 15360 B
#define SMEM64  (NSTG * STG64)           // 46080 B

__global__ __launch_bounds__(256, 2)
void tgemm64(const f16* __restrict__ Ah, int lda, int K,
             const f16* __restrict__ Bh, const float* __restrict__ bias,
             float* __restrict__ Cf, int ldcf,
             f16* __restrict__ Ch, int ldch)
{
    extern __shared__ __align__(128) char smem[];
    const uint32_t sb = smem_u32(smem);
    const int tid = threadIdx.x;
    const int bm = blockIdx.y * 64, bn = blockIdx.x * 128;
    const int KT = K / KC;

    const int ar = tid >> 2, as = tid & 3;
    const int br = tid >> 1, bs = (tid & 1) * 2;

    auto issue = [&](int c, int s) {
        const int ks = c * KC;
        const uint32_t abase = sb + (uint32_t)s * STG64 + (uint32_t)ar * AROW80;
        CP16(abase + (uint32_t)as * 16u, Ah + (size_t)(bm + ar) * lda + ks + as * 8);
        const f16* bh = Bh + (size_t)(bn + br) * K + ks;
        const uint32_t bbase = sb + (uint32_t)s * STG64 + TA64 + (uint32_t)br * AROW80;
#pragma unroll
        for (int g = 0; g < 2; g++) {
            const int seg = bs + g;
            CP16(bbase + (uint32_t)seg * 16u, bh + seg * 8);
        }
    };

    const int warp = tid >> 5, lane = tid & 31;
    const int wm = (warp & 1) * 32;
    const int wn = (warp >> 1) * 32;
    const int lr = lane & 7;
    const uint32_t aBase = (uint32_t)(wm + lr + ((lane >> 3) & 1) * 8) * AROW80
                         + (uint32_t)(((lane >> 4) & 1) * 8) * 2;
    const uint32_t bBase = (uint32_t)(wn + lr + ((lane >> 4) & 1) * 8) * AROW80
                         + (uint32_t)(((lane >> 3) & 1) * 8) * 2;

    float acc[2][4][4];
#pragma unroll
    for (int mi = 0; mi < 2; mi++)
#pragma unroll
        for (int j = 0; j < 4; j++)
#pragma unroll
            for (int q = 0; q < 4; q++) acc[mi][j][q] = 0.0f;

    issue(0, 0); CPCOMMIT();
    issue(1, 1); CPCOMMIT();

    for (int c = 0; c < KT; c++) {
        CPWAIT1();
        __syncthreads();
        if (c + 2 < KT) issue(c + 2, (c + 2) % NSTG);
        CPCOMMIT();
        const uint32_t st = sb + (uint32_t)(c % NSTG) * STG64;
#pragma unroll
        for (int k2 = 0; k2 < 2; k2++) {
            uint32_t ah[2][4];
#pragma unroll
            for (int mi = 0; mi < 2; mi++)
                LDSM4(ah[mi], st + aBase + (uint32_t)mi * (16 * AROW80)
                              + (uint32_t)k2 * 32);
#pragma unroll
            for (int jj = 0; jj < 2; jj++) {
                uint32_t b4[4];
                const uint32_t bo = st + TA64 + bBase
                                  + (uint32_t)jj * (16 * AROW80) + (uint32_t)k2 * 32;
                LDSM4(b4, bo);
                MMA(acc[0][2 * jj],     ah[0], b4[0], b4[1]);
                MMA(acc[1][2 * jj],     ah[1], b4[0], b4[1]);
                MMA(acc[0][2 * jj + 1], ah[0], b4[2], b4[3]);
                MMA(acc[1][2 * jj + 1], ah[1], b4[2], b4[3]);
            }
        }
    }

    const int r0 = bm + wm + (lane >> 2);
    const int c0 = bn + wn + 2 * (lane & 3);
#pragma unroll
    for (int mi = 0; mi < 2; mi++)
#pragma unroll
        for (int j = 0; j < 4; j++) {
            const int col = c0 + j * 8;
            float2 bs = *(const float2*)(bias + col);
#pragma unroll
            for (int h = 0; h < 2; h++) {
                const int row = r0 + mi * 16 + h * 8;
                float v0 = acc[mi][j][2 * h]     + bs.x;
                float v1 = acc[mi][j][2 * h + 1] + bs.y;
                if (Cf) *(float2*)(Cf + (size_t)row * ldcf + col) = make_float2(v0, v1);
                if (Ch) *(f162*)(Ch + (size_t)row * ldch + col) = __floats2half2_rn(v0, v1);
            }
        }
}

// ---------------- host -------------------------------------------------------
extern "C" void kernel_launch(void* const* d_in, const int* in_sizes, int n_in,
                              void* d_out, int out_size)
{
    const float* z       = (const float*)d_in[0];
    const float* td      = (const float*)d_in[1];
    const float* W_belta = (const float*)d_in[2];
    const float* b_belta = (const float*)d_in[3];
    const float* W_z     = (const float*)d_in[4];
    const float* b_z     = (const float*)d_in[5];
    const float* W1      = (const float*)d_in[6];
    const float* b1      = (const float*)d_in[7];
    const float* W2      = (const float*)d_in[8];
    const float* b2      = (const float*)d_in[9];
    const float* W3      = (const float*)d_in[10];
    const float* b3      = (const float*)d_in[11];
    const float* W_out   = (const float*)d_in[12];
    const float* b_out   = (const float*)d_in[13];
    float* out = (float*)d_out;

    float *stf, *spf, *uf;
    cudaGetSymbolAddress((void**)&stf, g_stf);
    cudaGetSymbolAddress((void**)&spf, g_spf);
    cudaGetSymbolAddress((void**)&uf,  g_uf);

    f16 *tdh, *zh, *sph, *sth, *rsh, *xh;
    cudaGetSymbolAddress((void**)&tdh, g_tdh);
    cudaGetSymbolAddress((void**)&zh,  g_zh);
    cudaGetSymbolAddress((void**)&sph, g_sph);
    cudaGetSymbolAddress((void**)&sth, g_sth);
    cudaGetSymbolAddress((void**)&rsh, g_rsh);
    cudaGetSymbolAddress((void**)&xh,  g_xh);

    f16 *W12h, *W3h, *Wbh, *Woh, *Wzh;
    cudaGetSymbolAddress((void**)&W12h, g_W12h);
    cudaGetSymbolAddress((void**)&W3h,  g_W3h);
    cudaGetSymbolAddress((void**)&Wbh,  g_Wbh);
    cudaGetSymbolAddress((void**)&Woh,  g_Woh);
    cudaGetSymbolAddress((void**)&Wzh,  g_Wzh);

    cudaFuncSetAttribute(tgemm<EPI_BELTA>, cudaFuncAttributeMaxDynamicSharedMemorySize, SMEM_T);
    cudaFuncSetAttribute(tgemm<EPI_NEW>,   cudaFuncAttributeMaxDynamicSharedMemorySize, SMEM_T);
    cudaFuncSetAttribute(tgemm512_sigur,   cudaFuncAttributeMaxDynamicSharedMemorySize, SMEM256);
    cudaFuncSetAttribute(tgemm64,          cudaFuncAttributeMaxDynamicSharedMemorySize, SMEM64);

    // ---- per-launch prep: 3 launches (deterministic for graph replay) ----
    zero_kernel<<<(B_DIM * H_DIM + 1023) / 1024, 1024>>>(stf, B_DIM * H_DIM);
    {
        const int n4a = (B_DIM * LDO) / 4;
        const int n4b = (B_DIM * ZDIM) / 4;
        ahalf2<<<(n4a + n4b + 255) / 256, 256>>>(td, n4a, tdh, z, n4b, zh);
    }
    wsplit_all<<<dim3(32, 48, 6), dim3(32, 8)>>>(W1, W2, W3, W_belta, W_out, W_z,
                                                 W12h, W3h, Wbh, Woh, Wzh);

    const dim3 blk(256);
    const dim3 gridH (H_DIM / 128,  B_DIM / 128);   // (8, 32)  BELTA / NEW
    const dim3 gridS (N12 / 128,    B_DIM / 256);   // (16, 16) SIGUR single wave
    const dim3 gridI64(IN_DIM / 128, B_DIM / 64);   // (4, 64)  x0 / OUT

    // x0 = z @ W_z + b_z  -> x fp16 only
    tgemm64<<<gridI64, blk, SMEM64>>>(zh, ZDIM, ZDIM, Wzh, b_z,
                                      nullptr, 0, xh, IN_DIM);

    for (int t = 0; t < SEQ_LEN; t++) {
        // spre = exp(-relu(td_t @ W_belta + b)) * state   (fp32 + fp16)
        tgemm<EPI_BELTA><<<gridH, blk, SMEM_T>>>(tdh + (size_t)t * IN_DIM, LDO, IN_DIM,
                                                 nullptr, 0, 0,
                                                 Wbh, b_belta, nullptr, stf, nullptr,
                                                 spf, H_DIM, sph, H_DIM);
        // fused: u = sig([spre|x]W1+b1) -> uf ;  rs = sig([spre|x]W2+b2)*spre -> fp16
        tgemm512_sigur<<<gridS, dim3(512), SMEM256>>>(sph, H_DIM, H_DIM,
                                                      xh, IN_DIM, IN_DIM,
                                                      W12h, b1, b2, spf,
                                                      uf, H_DIM, rsh, H_DIM);
        // state = (1-u)*spre + u*tanh([rs|x] @ W3 + b3)   (fp32 + fp16)
        tgemm<EPI_NEW><<<gridH, blk, SMEM_T>>>(rsh, H_DIM, H_DIM,
                                               xh, IN_DIM, IN_DIM,
                                               W3h, b3, nullptr, uf, spf,
                                               stf, H_DIM, sth, H_DIM);
        // out_t = state @ W_out + b_out  (strided into d_out + x fp16 feedback)
        tgemm64<<<gridI64, blk, SMEM64>>>(sth, H_DIM, H_DIM, Woh, b_out,
                                          out + (size_t)t * IN_DIM, LDO,
                                          xh, IN_DIM);
    }
}

// round 16
// speedup vs baseline: 1.9031x; 1.9031x over previous
#include <cuda_runtime.h>
#include <cuda_fp16.h>
#include <math.h>
#include <stdint.h>

#define B_DIM   4096
#define ZDIM    128
#define IN_DIM  512
#define H_DIM   1024
#define SEQ_LEN 12
#define CAT     (IN_DIM + H_DIM)
#define LDO     (SEQ_LEN * IN_DIM)
#define N12     (2 * H_DIM)

typedef __half  f16;
typedef __half2 f162;

// ---------------- scratch (__device__ globals; no allocs allowed) -----------
__device__ float g_stf[B_DIM * H_DIM];
__device__ float g_spf[B_DIM * H_DIM];
__device__ float g_uf [B_DIM * H_DIM];

__device__ f16 g_tdh[B_DIM * LDO];
__device__ f16 g_zh [B_DIM * ZDIM];
__device__ f16 g_sph[B_DIM * H_DIM];
__device__ f16 g_sth[B_DIM * H_DIM];
__device__ f16 g_rsh[B_DIM * H_DIM];
__device__ f16 g_xh [B_DIM * IN_DIM];

// weights transposed to [N][K] fp16
__device__ f16 g_W12h[N12 * CAT];          // W1 rows then W2 rows
__device__ f16 g_W3h [H_DIM * CAT];
__device__ f16 g_Wbh [H_DIM * IN_DIM];
__device__ f16 g_Woh [IN_DIM * H_DIM];
__device__ f16 g_Wzh [IN_DIM * ZDIM];

enum { EPI_LIN = 0, EPI_BELTA = 1, EPI_SIGUR = 2, EPI_NEW = 3 };

// ---------------- prep kernels (3 launches) ---------------------------------
__global__ void zero_kernel(float* __restrict__ p, int n) {
    int i = blockIdx.x * blockDim.x + threadIdx.x;
    if (i < n) p[i] = 0.0f;
}

__global__ void ahalf2(const float* __restrict__ A, int n4a, f16* __restrict__ Ha,
                       const float* __restrict__ Bv, int n4b, f16* __restrict__ Hb) {
    int i = blockIdx.x * blockDim.x + threadIdx.x;
    if (i < n4a) {
        float4 v = ((const float4*)A)[i];
        ((f162*)Ha)[2 * i]     = __floats2half2_rn(v.x, v.y);
        ((f162*)Ha)[2 * i + 1] = __floats2half2_rn(v.z, v.w);
    } else if (i < n4a + n4b) {
        int j = i - n4a;
        float4 v = ((const float4*)Bv)[j];
        ((f162*)Hb)[2 * j]     = __floats2half2_rn(v.x, v.y);
        ((f162*)Hb)[2 * j + 1] = __floats2half2_rn(v.z, v.w);
    }
}

__global__ void wsplit_all(const float* __restrict__ W1, const float* __restrict__ W2,
                           const float* __restrict__ W3, const float* __restrict__ Wb,
                           const float* __restrict__ Wo, const float* __restrict__ Wz,
                           f16* __restrict__ T12, f16* __restrict__ T3,
                           f16* __restrict__ Tb, f16* __restrict__ To,
                           f16* __restrict__ Tz) {
    const float* W; f16* T; int K, N;
    switch (blockIdx.z) {
        case 0: W = W1; T = T12;                        K = CAT;    N = H_DIM;  break;
        case 1: W = W2; T = T12 + (size_t)H_DIM * CAT;  K = CAT;    N = H_DIM;  break;
        case 2: W = W3; T = T3;                         K = CAT;    N = H_DIM;  break;
        case 3: W = Wb; T = Tb;                         K = IN_DIM; N = H_DIM;  break;
        case 4: W = Wo; T = To;                         K = H_DIM;  N = IN_DIM; break;
        default: W = Wz; T = Tz;                        K = ZDIM;   N = IN_DIM; break;
    }
    const int n0 = blockIdx.x * 32, k0 = blockIdx.y * 32;
    if (n0 >= N || k0 >= K) return;
    __shared__ float t[32][33];
    const int tx = threadIdx.x, ty = threadIdx.y;   // (32, 8)
#pragma unroll
    for (int j = 0; j < 32; j += 8)
        t[ty + j][tx] = W[(size_t)(k0 + ty + j) * N + (n0 + tx)];
    __syncthreads();
#pragma unroll
    for (int j = 0; j < 32; j += 8)
        T[(size_t)(n0 + ty + j) * K + (k0 + tx)] = __float2half_rn(t[tx][ty + j]);
}

// ---------------- PTX primitives --------------------------------------------
__device__ __forceinline__ uint32_t smem_u32(const void* p) {
    uint32_t a;
    asm("{ .reg .u64 t; cvta.to.shared.u64 t, %1; cvt.u32.u64 %0, t; }" : "=r"(a) : "l"(p));
    return a;
}

#define CP16(dst, src) \
    asm volatile("cp.async.ca.shared.global [%0], [%1], 16;" :: "r"(dst), "l"(src) : "memory")
#define CPCOMMIT() asm volatile("cp.async.commit_group;" ::: "memory")
#define CPWAIT1()  asm volatile("cp.async.wait_group 1;"  ::: "memory")

#define GDC_WAIT()   asm volatile("griddepcontrol.wait;" ::: "memory")
#define GDC_LAUNCH() asm volatile("griddepcontrol.launch_dependents;" ::: "memory")

#define LDSM4(r, a) \
    asm volatile("ldmatrix.sync.aligned.m8n8.x4.shared.b16 {%0,%1,%2,%3}, [%4];" \
        : "=r"((r)[0]), "=r"((r)[1]), "=r"((r)[2]), "=r"((r)[3]) : "r"(a))

#define MMA(c, a, b0, b1) \
    asm volatile("mma.sync.aligned.m16n8k16.row.col.f32.f16.f16.f32 " \
        "{%0,%1,%2,%3}, {%4,%5,%6,%7}, {%8,%9}, {%0,%1,%2,%3};" \
        : "+f"((c)[0]), "+f"((c)[1]), "+f"((c)[2]), "+f"((c)[3]) \
        : "r"((a)[0]), "r"((a)[1]), "r"((a)[2]), "r"((a)[3]), "r"(b0), "r"(b1))

// ---------------- 128x128 HMMA GEMM with fused epilogue (R13 core + PDL) ----
#define KC      32
#define AROW80  80
#define TILE_B  (128 * AROW80)           // 10240 B
#define STAGE   (2 * TILE_B)             // A, B = 20480 B
#define NSTG    3
#define SMEM_T  (NSTG * STAGE)           // 61440 B

template <int EPI>
__global__ __launch_bounds__(256, 2)
void tgemm(const f16* __restrict__ Ah1, int lda1, int K1,
           const f16* __restrict__ Ah2, int lda2, int K2,
           const f16* __restrict__ Bh,
           const float* __restrict__ bias, const float* __restrict__ bias2,
           const float* __restrict__ ex1, const float* __restrict__ ex2,
           float* __restrict__ Cf, int ldcf,
           f16* __restrict__ Ch, int ldch)
{
    extern __shared__ __align__(128) char smem[];
    const uint32_t sb = smem_u32(smem);
    const int tid = threadIdx.x;
    const int bm = blockIdx.y * 128, bn = blockIdx.x * 128;
    const int Ktot = K1 + K2;
    const int KT = Ktot / KC;

    const int cr = tid >> 1;
    const int cs = (tid & 1) * 2;

    auto issueB = [&](int c, int s) {
        const int ks = c * KC;
        const f16* bh = Bh + (size_t)(bn + cr) * Ktot + ks;
        const uint32_t base = sb + (uint32_t)s * STAGE + (uint32_t)cr * AROW80;
#pragma unroll
        for (int g = 0; g < 2; g++) {
            const int seg = cs + g;
            CP16(base + TILE_B + (uint32_t)seg * 16u, bh + seg * 8);
        }
    };
    auto issueA = [&](int c, int s) {
        const int ks = c * KC;
        const f16* ah = (ks < K1)
            ? Ah1 + (size_t)(bm + cr) * lda1 + ks
            : Ah2 + (size_t)(bm + cr) * lda2 + (ks - K1);
        const uint32_t base = sb + (uint32_t)s * STAGE + (uint32_t)cr * AROW80;
#pragma unroll
        for (int g = 0; g < 2; g++) {
            const int seg = cs + g;
            CP16(base + (uint32_t)seg * 16u, ah + seg * 8);
        }
    };

    const int warp = tid >> 5, lane = tid & 31;
    const int wm = (warp & 3) * 32;
    const int wn = (warp >> 2) * 64;
    const int lr = lane & 7;
    const uint32_t aBase = (uint32_t)(wm + lr + ((lane >> 3) & 1) * 8) * AROW80
                         + (uint32_t)(((lane >> 4) & 1) * 8) * 2;
    const uint32_t bBase = (uint32_t)(wn + lr + ((lane >> 4) & 1) * 8) * AROW80
                         + (uint32_t)(((lane >> 3) & 1) * 8) * 2;

    float acc[2][8][4];
#pragma unroll
    for (int mi = 0; mi < 2; mi++)
#pragma unroll
        for (int j = 0; j < 8; j++)
#pragma unroll
            for (int q = 0; q < 4; q++) acc[mi][j][q] = 0.0f;

    // PDL: weight prefetch has no dependency on the predecessor
    issueB(0, 0);
    issueB(1, 1);
    GDC_WAIT();
    issueA(0, 0); CPCOMMIT();   // group0 = {B0, B1, A0}
    issueA(1, 1); CPCOMMIT();   // group1 = {A1}

    for (int c = 0; c < KT; c++) {
        CPWAIT1();
        __syncthreads();
        if (c + 2 < KT) { issueA(c + 2, (c + 2) % NSTG); issueB(c + 2, (c + 2) % NSTG); }
        CPCOMMIT();
        const uint32_t st = sb + (uint32_t)(c % NSTG) * STAGE;
#pragma unroll
        for (int k2 = 0; k2 < 2; k2++) {
            uint32_t ah[2][4];
#pragma unroll
            for (int mi = 0; mi < 2; mi++)
                LDSM4(ah[mi], st + aBase + (uint32_t)mi * (16 * AROW80)
                              + (uint32_t)k2 * 32);
#pragma unroll
            for (int jj = 0; jj < 4; jj++) {
                uint32_t b4[4];
                const uint32_t bo = st + TILE_B + bBase
                                  + (uint32_t)jj * (16 * AROW80) + (uint32_t)k2 * 32;
                LDSM4(b4, bo);
                MMA(acc[0][2 * jj],     ah[0], b4[0], b4[1]);
                MMA(acc[1][2 * jj],     ah[1], b4[0], b4[1]);
                MMA(acc[0][2 * jj + 1], ah[0], b4[2], b4[3]);
                MMA(acc[1][2 * jj + 1], ah[1], b4[2], b4[3]);
            }
        }
    }

    GDC_LAUNCH();   // mainloop done: let the dependent grid start its prologue

    // --- epilogue ---
    const int r0 = bm + wm + (lane >> 2);
    const int c0 = bn + wn + 2 * (lane & 3);

    auto dopair = [&](int row, int col, float v0, float v1) {
        if (EPI == EPI_SIGUR) {
            if (col < H_DIM) {
                float2 bs = *(const float2*)(bias + col);
                v0 = 1.0f / (1.0f + __expf(-(v0 + bs.x)));
                v1 = 1.0f / (1.0f + __expf(-(v1 + bs.y)));
                *(float2*)(Cf + (size_t)row * ldcf + col) = make_float2(v0, v1);
            } else {
                const int cc = col - H_DIM;
                float2 bs = *(const float2*)(bias2 + cc);
                float2 e  = *(const float2*)(ex1 + (size_t)row * H_DIM + cc);
                v0 = e.x / (1.0f + __expf(-(v0 + bs.x)));
                v1 = e.y / (1.0f + __expf(-(v1 + bs.y)));
                *(f162*)(Ch + (size_t)row * ldch + cc) = __floats2half2_rn(v0, v1);
            }
            return;
        }
        float2 bs = *(const float2*)(bias + col);
        v0 += bs.x; v1 += bs.y;
        if (EPI == EPI_BELTA) {
            float2 e = *(const float2*)(ex1 + (size_t)row * H_DIM + col);
            v0 = __expf(-fmaxf(v0, 0.0f)) * e.x;
            v1 = __expf(-fmaxf(v1, 0.0f)) * e.y;
        } else if (EPI == EPI_NEW) {
            float2 eu = *(const float2*)(ex1 + (size_t)row * H_DIM + col);
            float2 es = *(const float2*)(ex2 + (size_t)row * H_DIM + col);
            v0 = (1.0f - eu.x) * es.x + eu.x * tanhf(v0);
            v1 = (1.0f - eu.y) * es.y + eu.y * tanhf(v1);
        }
        if (Cf) *(float2*)(Cf + (size_t)row * ldcf + col) = make_float2(v0, v1);
        if (Ch) *(f162*)(Ch + (size_t)row * ldch + col) = __floats2half2_rn(v0, v1);
    };

#pragma unroll
    for (int mi = 0; mi < 2; mi++)
#pragma unroll
        for (int j = 0; j < 8; j++) {
            const int row = r0 + mi * 16;
            const int col = c0 + j * 8;
            dopair(row,     col, acc[mi][j][0], acc[mi][j][1]);
            dopair(row + 8, col, acc[mi][j][2], acc[mi][j][3]);
        }
}

// ---------------- 64x128 LIN GEMM (OUT / x0) + PDL --------------------------
#define TA64    (64 * AROW80)            // 5120 B
#define STG64   (TA64 + TILE_B)          // 15360 B
#define SMEM64  (NSTG * STG64)           // 46080 B

__global__ __launch_bounds__(256, 2)
void tgemm64(const f16* __restrict__ Ah, int lda, int K,
             const f16* __restrict__ Bh, const float* __restrict__ bias,
             float* __restrict__ Cf, int ldcf,
             f16* __restrict__ Ch, int ldch)
{
    extern __shared__ __align__(128) char smem[];
    const uint32_t sb = smem_u32(smem);
    const int tid = threadIdx.x;
    const int bm = blockIdx.y * 64, bn = blockIdx.x * 128;
    const int KT = K / KC;

    const int ar = tid >> 2, as = tid & 3;
    const int br = tid >> 1, bs = (tid & 1) * 2;

    auto issueB = [&](int c, int s) {
        const int ks = c * KC;
        const f16* bh = Bh + (size_t)(bn + br) * K + ks;
        const uint32_t bbase = sb + (uint32_t)s * STG64 + TA64 + (uint32_t)br * AROW80;
#pragma unroll
        for (int g = 0; g < 2; g++) {
            const int seg = bs + g;
            CP16(bbase + (uint32_t)seg * 16u, bh + seg * 8);
        }
    };
    auto issueA = [&](int c, int s) {
        const int ks = c * KC;
        const uint32_t abase = sb + (uint32_t)s * STG64 + (uint32_t)ar * AROW80;
        CP16(abase + (uint32_t)as * 16u, Ah + (size_t)(bm + ar) * lda + ks + as * 8);
    };

    const int warp = tid >> 5, lane = tid & 31;
    const int wm = (warp & 1) * 32;
    const int wn = (warp >> 1) * 32;
    const int lr = lane & 7;
    const uint32_t aBase = (uint32_t)(wm + lr + ((lane >> 3) & 1) * 8) * AROW80
                         + (uint32_t)(((lane >> 4) & 1) * 8) * 2;
    const uint32_t bBase = (uint32_t)(wn + lr + ((lane >> 4) & 1) * 8) * AROW80
                         + (uint32_t)(((lane >> 3) & 1) * 8) * 2;

    float acc[2][4][4];
#pragma unroll
    for (int mi = 0; mi < 2; mi++)
#pragma unroll
        for (int j = 0; j < 4; j++)
#pragma unroll
            for (int q = 0; q < 4; q++) acc[mi][j][q] = 0.0f;

    issueB(0, 0);
    issueB(1, 1);
    GDC_WAIT();
    issueA(0, 0); CPCOMMIT();
    issueA(1, 1); CPCOMMIT();

    for (int c = 0; c < KT; c++) {
        CPWAIT1();
        __syncthreads();
        if (c + 2 < KT) { issueA(c + 2, (c + 2) % NSTG); issueB(c + 2, (c + 2) % NSTG); }
        CPCOMMIT();
        const uint32_t st = sb + (uint32_t)(c % NSTG) * STG64;
#pragma unroll
        for (int k2 = 0; k2 < 2; k2++) {
            uint32_t ah[2][4];
#pragma unroll
            for (int mi = 0; mi < 2; mi++)
                LDSM4(ah[mi], st + aBase + (uint32_t)mi * (16 * AROW80)
                              + (uint32_t)k2 * 32);
#pragma unroll
            for (int jj = 0; jj < 2; jj++) {
                uint32_t b4[4];
                const uint32_t bo = st + TA64 + bBase
                                  + (uint32_t)jj * (16 * AROW80) + (uint32_t)k2 * 32;
                LDSM4(b4, bo);
                MMA(acc[0][2 * jj],     ah[0], b4[0], b4[1]);
                MMA(acc[1][2 * jj],     ah[1], b4[0], b4[1]);
                MMA(acc[0][2 * jj + 1], ah[0], b4[2], b4[3]);
                MMA(acc[1][2 * jj + 1], ah[1], b4[2], b4[3]);
            }
        }
    }

    GDC_LAUNCH();

    const int r0 = bm + wm + (lane >> 2);
    const int c0 = bn + wn + 2 * (lane & 3);
#pragma unroll
    for (int mi = 0; mi < 2; mi++)
#pragma unroll
        for (int j = 0; j < 4; j++) {
            const int col = c0 + j * 8;
            float2 bs = *(const float2*)(bias + col);
#pragma unroll
            for (int h = 0; h < 2; h++) {
                const int row = r0 + mi * 16 + h * 8;
                float v0 = acc[mi][j][2 * h]     + bs.x;
                float v1 = acc[mi][j][2 * h + 1] + bs.y;
                if (Cf) *(float2*)(Cf + (size_t)row * ldcf + col) = make_float2(v0, v1);
                if (Ch) *(f162*)(Ch + (size_t)row * ldch + col) = __floats2half2_rn(v0, v1);
            }
        }
}

// ---------------- host -------------------------------------------------------
extern "C" void kernel_launch(void* const* d_in, const int* in_sizes, int n_in,
                              void* d_out, int out_size)
{
    const float* z       = (const float*)d_in[0];
    const float* td      = (const float*)d_in[1];
    const float* W_belta = (const float*)d_in[2];
    const float* b_belta = (const float*)d_in[3];
    const float* W_z     = (const float*)d_in[4];
    const float* b_z     = (const float*)d_in[5];
    const float* W1      = (const float*)d_in[6];
    const float* b1      = (const float*)d_in[7];
    const float* W2      = (const float*)d_in[8];
    const float* b2      = (const float*)d_in[9];
    const float* W3      = (const float*)d_in[10];
    const float* b3      = (const float*)d_in[11];
    const float* W_out   = (const float*)d_in[12];
    const float* b_out   = (const float*)d_in[13];
    float* out = (float*)d_out;

    float *stf, *spf, *uf;
    cudaGetSymbolAddress((void**)&stf, g_stf);
    cudaGetSymbolAddress((void**)&spf, g_spf);
    cudaGetSymbolAddress((void**)&uf,  g_uf);

    f16 *tdh, *zh, *sph, *sth, *rsh, *xh;
    cudaGetSymbolAddress((void**)&tdh, g_tdh);
    cudaGetSymbolAddress((void**)&zh,  g_zh);
    cudaGetSymbolAddress((void**)&sph, g_sph);
    cudaGetSymbolAddress((void**)&sth, g_sth);
    cudaGetSymbolAddress((void**)&rsh, g_rsh);
    cudaGetSymbolAddress((void**)&xh,  g_xh);

    f16 *W12h, *W3h, *Wbh, *Woh, *Wzh;
    cudaGetSymbolAddress((void**)&W12h, g_W12h);
    cudaGetSymbolAddress((void**)&W3h,  g_W3h);
    cudaGetSymbolAddress((void**)&Wbh,  g_Wbh);
    cudaGetSymbolAddress((void**)&Woh,  g_Woh);
    cudaGetSymbolAddress((void**)&Wzh,  g_Wzh);

    cudaFuncSetAttribute(tgemm<EPI_BELTA>, cudaFuncAttributeMaxDynamicSharedMemorySize, SMEM_T);
    cudaFuncSetAttribute(tgemm<EPI_SIGUR>, cudaFuncAttributeMaxDynamicSharedMemorySize, SMEM_T);
    cudaFuncSetAttribute(tgemm<EPI_NEW>,   cudaFuncAttributeMaxDynamicSharedMemorySize, SMEM_T);
    cudaFuncSetAttribute(tgemm64,          cudaFuncAttributeMaxDynamicSharedMemorySize, SMEM64);

    // ---- per-launch prep: 3 launches (deterministic for graph replay) ----
    zero_kernel<<<(B_DIM * H_DIM + 1023) / 1024, 1024>>>(stf, B_DIM * H_DIM);
    {
        const int n4a = (B_DIM * LDO) / 4;
        const int n4b = (B_DIM * ZDIM) / 4;
        ahalf2<<<(n4a + n4b + 255) / 256, 256>>>(td, n4a, tdh, z, n4b, zh);
    }
    wsplit_all<<<dim3(32, 48, 6), dim3(32, 8)>>>(W1, W2, W3, W_belta, W_out, W_z,
                                                 W12h, W3h, Wbh, Woh, Wzh);

    // PDL launch config
    cudaLaunchAttribute pdl[1];
    pdl[0].id = cudaLaunchAttributeProgrammaticStreamSerialization;
    pdl[0].val.programmaticStreamSerializationAllowed = 1;

    auto cfg = [&](dim3 g, size_t smem) {
        cudaLaunchConfig_t c{};
        c.gridDim = g;
        c.blockDim = dim3(256);
        c.dynamicSmemBytes = smem;
        c.stream = (cudaStream_t)0;
        c.attrs = pdl;
        c.numAttrs = 1;
        return c;
    };

    const dim3 gridH (H_DIM / 128,  B_DIM / 128);   // (8, 32)  BELTA / NEW
    const dim3 gridH2(N12 / 128,    B_DIM / 128);   // (16, 32) SIGUR
    const dim3 gridI64(IN_DIM / 128, B_DIM / 64);   // (4, 64)  x0 / OUT

    // x0 = z @ W_z + b_z  -> x fp16 only
    {
        cudaLaunchConfig_t c = cfg(gridI64, SMEM64);
        cudaLaunchKernelEx(&c, tgemm64, zh, ZDIM, ZDIM, Wzh, b_z,
                           (float*)nullptr, 0, xh, IN_DIM);
    }

    for (int t = 0; t < SEQ_LEN; t++) {
        // spre = exp(-relu(td_t @ W_belta + b)) * state
        {
            cudaLaunchConfig_t c = cfg(gridH, SMEM_T);
            cudaLaunchKernelEx(&c, tgemm<EPI_BELTA>,
                               (const f16*)(tdh + (size_t)t * IN_DIM), LDO, IN_DIM,
                               (const f16*)nullptr, 0, 0,
                               (const f16*)Wbh, b_belta, (const float*)nullptr,
                               (const float*)stf, (const float*)nullptr,
                               spf, H_DIM, sph, H_DIM);
        }
        // fused: u = sig([spre|x]W1+b1) -> uf ;  rs = sig([spre|x]W2+b2)*spre
        {
            cudaLaunchConfig_t c = cfg(gridH2, SMEM_T);
            cudaLaunchKernelEx(&c, tgemm<EPI_SIGUR>,
                               (const f16*)sph, H_DIM, H_DIM,
                               (const f16*)xh, IN_DIM, IN_DIM,
                               (const f16*)W12h, b1, b2,
                               (const float*)spf, (const float*)nullptr,
                               uf, H_DIM, rsh, H_DIM);
        }
        // state = (1-u)*spre + u*tanh([rs|x] @ W3 + b3)
        {
            cudaLaunchConfig_t c = cfg(gridH, SMEM_T);
            cudaLaunchKernelEx(&c, tgemm<EPI_NEW>,
                               (const f16*)rsh, H_DIM, H_DIM,
                               (const f16*)xh, IN_DIM, IN_DIM,
                               (const f16*)W3h, b3, (const float*)nullptr,
                               (const float*)uf, (const float*)spf,
                               stf, H_DIM, sth, H_DIM);
        }
        // out_t = state @ W_out + b_out  (strided into d_out + x fp16 feedback)
        {
            cudaLaunchConfig_t c = cfg(gridI64, SMEM64);
            cudaLaunchKernelEx(&c, tgemm64,
                               (const f16*)sth, H_DIM, H_DIM,
                               (const f16*)Woh, b_out,
                               out + (size_t)t * IN_DIM, LDO,
                               xh, IN_DIM);
        }
    }
}